// round 5
// baseline (speedup 1.0000x reference)
#include <cuda_runtime.h>
#include <cstdint>

// FPS: B=2 batches, Npb=131072 pts, stride=32 -> M=4096 samples.
// 64 CTAs/batch (128 total, one per SM, single wave) * 256 threads * 8 pts.
// Per-round batch argmax via 64 candidate slots in L2; each slot is two
// self-validating 16B halves (freshness word + payload in the same 16B L2
// access -> single round trip, no acquire/release). Parity double-buffered.
// ALL warps poll and reduce the slots redundantly -> one __syncthreads per
// round and no broadcast stage.

#define NBATCH 2
#define CPB    64     // CTAs per batch
#define TPB    256    // 8 warps
#define PPT    8      // points per thread  (CPB*TPB*PPT = 131072)
#define NPB    131072
#define MSAMP  4096
#define NW     (TPB / 32)

struct __align__(32) Slot { uint4 a; uint4 b; };
// halfA = {dist_bits, w, x, y}   halfB = {z, w, 0, 0}
// w = (t << 17) | (tail & 0x1FFFF),  tail = 0x7FFFFFFF - in_batch_idx

__device__ Slot g_slot[2][NBATCH][CPB];   // [parity][batch][cta]

__device__ __forceinline__ uint4 ldv(const uint4* p) {
    uint4 v;
    asm volatile("ld.volatile.global.v4.u32 {%0,%1,%2,%3}, [%4];"
                 : "=r"(v.x), "=r"(v.y), "=r"(v.z), "=r"(v.w) : "l"(p));
    return v;
}
__device__ __forceinline__ void stv(uint4* p, uint4 v) {
    asm volatile("st.volatile.global.v4.u32 [%0], {%1,%2,%3,%4};"
                 :: "l"(p), "r"(v.x), "r"(v.y), "r"(v.z), "r"(v.w));
}

__global__ void __launch_bounds__(TPB, 1)
fps_kernel(const float4* __restrict__ pts, float* __restrict__ out)
{
    const int c    = blockIdx.x;          // CTA within batch (0..63)
    const int b    = blockIdx.y;          // batch
    const int tid  = threadIdx.x;
    const int lane = tid & 31;
    const int wid  = tid >> 5;

    const int lbase = c * (TPB * PPT);    // in-batch base index of this CTA
    const int gbase = b * NPB + lbase;

    // Register-resident point state
    float x[PPT], y[PPT], z[PPT], dist[PPT];
    unsigned tail[PPT];
#pragma unroll
    for (int p = 0; p < PPT; ++p) {
        float4 v = pts[gbase + p * TPB + tid];
        x[p] = v.y; y[p] = v.z; z[p] = v.w;
        dist[p] = 3.402823466e38f;        // +FLT_MAX: round 1 min == d(.,p0)
        tail[p] = 0x7FFFFFFFu - (unsigned)(lbase + p * TPB + tid);
    }

    // Seed sample = point 0 of the batch
    float4 p0 = pts[(size_t)b * NPB];
    float sx = p0.y, sy = p0.z, sz = p0.w;
    if (c == 0 && tid == 0) {
        float* o = out + (size_t)b * MSAMP * 4;
        o[0] = p0.x; o[1] = p0.y; o[2] = p0.z; o[3] = p0.w;
    }

    __shared__ unsigned s_db[NW], s_tl[NW];
    __shared__ float    s_x[NW], s_y[NW], s_z[NW];

    for (int t = 1; t < MSAMP; ++t) {
        const unsigned tgt = (unsigned)t;

        // ---- local dist update + per-thread argmax (bit compare == float
        // compare for non-negative f32; strict > keeps lowest index because
        // equal-dist later points have smaller tail -> matches jnp.argmax) ----
        unsigned bdb = 0u, btl = 0u;
        float bx = 0.f, by = 0.f, bz = 0.f;
#pragma unroll
        for (int p = 0; p < PPT; ++p) {
            float dx = x[p] - sx;
            float dy = y[p] - sy;
            float dz = z[p] - sz;
            // unfused, left-to-right (dx*dx + dy*dy) + dz*dz == reference
            float d  = __fadd_rn(__fadd_rn(__fmul_rn(dx, dx), __fmul_rn(dy, dy)),
                                 __fmul_rn(dz, dz));
            float nd = fminf(dist[p], d);
            dist[p]  = nd;
            unsigned db = __float_as_uint(nd);
            if (db > bdb) { bdb = db; btl = tail[p]; bx = x[p]; by = y[p]; bz = z[p]; }
        }

        // ---- warp argmax (max dist-bits, tie -> max tail = lowest index) ----
        unsigned m  = __reduce_max_sync(0xFFFFFFFFu, bdb);
        unsigned tv = (bdb == m) ? btl : 0u;
        unsigned mt = __reduce_max_sync(0xFFFFFFFFu, tv);
        if (bdb == m && btl == mt) {
            s_db[wid] = bdb; s_tl[wid] = btl;
            s_x[wid] = bx; s_y[wid] = by; s_z[wid] = bz;
        }
        __syncthreads();   // the ONLY barrier in the round

        // ---- warp 0: block argmax over NW warp winners, publish candidate ----
        if (wid == 0) {
            unsigned db2 = 0u, tl2 = 0u;
            float x2 = 0.f, y2 = 0.f, z2 = 0.f;
            if (lane < NW) {
                db2 = s_db[lane]; tl2 = s_tl[lane];
                x2 = s_x[lane]; y2 = s_y[lane]; z2 = s_z[lane];
            }
            unsigned m2  = __reduce_max_sync(0xFFFFFFFFu, db2);
            unsigned tv2 = (db2 == m2) ? tl2 : 0u;
            unsigned mt2 = __reduce_max_sync(0xFFFFFFFFu, tv2);
            if (db2 == m2 && tl2 == mt2) {
                unsigned w = (tgt << 17) | (tl2 & 0x1FFFFu);
                Slot* sp = &g_slot[t & 1][b][c];
                stv(&sp->b, make_uint4(__float_as_uint(z2), w, 0u, 0u));
                stv(&sp->a, make_uint4(db2, w, __float_as_uint(x2),
                                       __float_as_uint(y2)));
            }
        }

        // ---- EVERY warp: poll all 64 slots (2 per lane) + batch argmax ----
        {
            Slot* s0 = &g_slot[t & 1][b][lane];
            Slot* s1 = &g_slot[t & 1][b][lane + 32];
            uint4 A0, B0, A1, B1;
            do {
                A0 = ldv(&s0->a); B0 = ldv(&s0->b);
                A1 = ldv(&s1->a); B1 = ldv(&s1->b);
            } while ((A0.y >> 17) != tgt || (B0.y >> 17) != tgt ||
                     (A1.y >> 17) != tgt || (B1.y >> 17) != tgt);

            // fold the lane's two candidates
            unsigned db3 = A0.x, w3 = A0.y;
            float fx = __uint_as_float(A0.z), fy = __uint_as_float(A0.w);
            float fz = __uint_as_float(B0.x);
            if (A1.x > db3 || (A1.x == db3 && (A1.y & 0x1FFFFu) > (w3 & 0x1FFFFu))) {
                db3 = A1.x; w3 = A1.y;
                fx = __uint_as_float(A1.z); fy = __uint_as_float(A1.w);
                fz = __uint_as_float(B1.x);
            }
            unsigned tl3 = 0x7FFE0000u | (w3 & 0x1FFFFu);

            unsigned m3  = __reduce_max_sync(0xFFFFFFFFu, db3);
            unsigned tv3 = (db3 == m3) ? tl3 : 0u;
            unsigned mt3 = __reduce_max_sync(0xFFFFFFFFu, tv3);
            int win = (db3 == m3 && tl3 == mt3);

            // broadcast winner xyz within the warp (exactly one winning lane)
            unsigned wl = 31 - __clz(__ballot_sync(0xFFFFFFFFu, win));
            sx = __shfl_sync(0xFFFFFFFFu, fx, wl);
            sy = __shfl_sync(0xFFFFFFFFu, fy, wl);
            sz = __shfl_sync(0xFFFFFFFFu, fz, wl);

            if (c == 0 && wid == 0 && lane == (int)wl) {
                float* o = out + ((size_t)b * MSAMP + t) * 4;
                o[0] = (float)b; o[1] = fx; o[2] = fy; o[3] = fz;
            }
        }
        // no second barrier: every warp now holds the new sample in registers
    }
}

extern "C" void kernel_launch(void* const* d_in, const int* in_sizes, int n_in,
                              void* d_out, int out_size) {
    (void)in_sizes; (void)n_in; (void)out_size;
    const float4* pts = (const float4*)d_in[0];
    // Geometry fixed by the problem instance: N=262144, B=2, stride=32.
    dim3 grid(CPB, NBATCH);
    fps_kernel<<<grid, TPB>>>(pts, (float*)d_out);
}

// round 7
// speedup vs baseline: 3.4869x; 3.4869x over previous
#include <cuda_runtime.h>
#include <cstdint>

// FPS: B=2, Npb=131072, stride=32 -> M=4096 samples, 4095 serial rounds.
// 64 CTAs/batch * 256 thr * 8 pts/thr (128 CTAs total: single wave, spin-safe).
// Per-round batch argmax is computed BY THE L2 ATOMIC UNIT: each CTA
// red.max's key = (round<<49 | dist_bits<<17 | tail17) and red.release.add's
// a counter on ONE line per (batch, parity). warp0 polls the 4B counter with
// ld.acquire (broadcast address); once cnt >= 64*ceil(t/2), a SEPARATE
// ld.relaxed.u64 (ordered after the acquire) reads the final key -- this
// two-step read fixes the R6 vector-load tearing race (vector element reads
// are unordered; cnt could be seen new with key stale). Winner coords are
// re-fetched from pts[idx]. Reset kernel clears lines every launch.

#define NBATCH 2
#define CPB    64
#define TPB    256
#define PPT    8       // CPB*TPB*PPT = 131072
#define NPB    131072
#define MSAMP  4096
#define NW     (TPB / 32)
#define FLTMAX 3.402823466e38f

typedef unsigned long long u64;

struct __align__(16) Line { u64 key; unsigned cnt; unsigned _p; u64 _pad[14]; };
__device__ Line g_line[2][NBATCH];   // [round parity][batch], 128B apart

__global__ void reset_kernel() {
    int i = threadIdx.x;
    if (i < 2 * NBATCH) {
        g_line[i >> 1][i & 1].key = 0ULL;
        g_line[i >> 1][i & 1].cnt = 0u;
    }
}

__device__ __forceinline__ u64 f2pack(float lo, float hi) {
    u64 r; asm("mov.b64 %0, {%1,%2};" : "=l"(r) : "f"(lo), "f"(hi)); return r;
}
__device__ __forceinline__ void f2unpack(float& lo, float& hi, u64 v) {
    asm("mov.b64 {%0,%1}, %2;" : "=f"(lo), "=f"(hi) : "l"(v));
}
__device__ __forceinline__ u64 addx2(u64 a, u64 b) {   // per-lane IEEE rn add
    u64 r; asm("add.rn.f32x2 %0, %1, %2;" : "=l"(r) : "l"(a), "l"(b)); return r;
}
__device__ __forceinline__ u64 mulx2(u64 a, u64 b) {   // per-lane IEEE rn mul
    u64 r; asm("mul.rn.f32x2 %0, %1, %2;" : "=l"(r) : "l"(a), "l"(b)); return r;
}
__device__ __forceinline__ void red_max_u64(u64* p, u64 v) {
    asm volatile("red.relaxed.gpu.global.max.u64 [%0], %1;" :: "l"(p), "l"(v));
}
__device__ __forceinline__ void red_add_rel(unsigned* p, unsigned v) {
    asm volatile("red.release.gpu.global.add.u32 [%0], %1;" :: "l"(p), "r"(v));
}
__device__ __forceinline__ unsigned ld_acq_u32(const unsigned* p) {
    unsigned v;
    asm volatile("ld.acquire.gpu.global.u32 %0, [%1];" : "=r"(v) : "l"(p));
    return v;
}
__device__ __forceinline__ u64 ld_rlx_u64(const u64* p) {
    u64 v;
    asm volatile("ld.relaxed.gpu.global.u64 %0, [%1];" : "=l"(v) : "l"(p));
    return v;
}

__global__ void __launch_bounds__(TPB, 1)
fps_kernel(const float4* __restrict__ pts, float* __restrict__ out)
{
    const int c    = blockIdx.x;          // CTA within batch (0..63)
    const int b    = blockIdx.y;          // batch
    const int tid  = threadIdx.x;
    const int lane = tid & 31;
    const int wid  = tid >> 5;

    const int lbase = c * (TPB * PPT);    // in-batch base index of this CTA
    const int gbase = b * NPB + lbase;

    // Register-resident point state; coords packed 2-per-u64 for f32x2 math.
    u64 x2[PPT / 2], y2[PPT / 2], z2[PPT / 2];
    float dist[PPT];
    unsigned tail[PPT];                   // 0x1FFFF - in_batch_idx (17 bits)
#pragma unroll
    for (int i = 0; i < PPT / 2; ++i) {
        float4 v0 = pts[gbase + (2 * i) * TPB + tid];
        float4 v1 = pts[gbase + (2 * i + 1) * TPB + tid];
        x2[i] = f2pack(v0.y, v1.y);
        y2[i] = f2pack(v0.z, v1.z);
        z2[i] = f2pack(v0.w, v1.w);
        dist[2 * i] = FLTMAX; dist[2 * i + 1] = FLTMAX;
        tail[2 * i]     = 0x1FFFFu - (unsigned)(lbase + (2 * i) * TPB + tid);
        tail[2 * i + 1] = 0x1FFFFu - (unsigned)(lbase + (2 * i + 1) * TPB + tid);
    }

    // Seed sample = point 0 of the batch (pointops convention)
    float4 p0 = pts[(size_t)b * NPB];
    float sx = p0.y, sy = p0.z, sz = p0.w;
    if (c == 0 && tid == 0)
        ((float4*)out)[(size_t)b * MSAMP] = p0;

    __shared__ unsigned s_db[NW], s_tl[NW];
    __shared__ float    s_new[3];

    for (int t = 1; t < MSAMP; ++t) {
        // negate once (exact); x + (-s) is bit-identical to x - s in rn
        u64 nsx = f2pack(-sx, -sx);
        u64 nsy = f2pack(-sy, -sy);
        u64 nsz = f2pack(-sz, -sz);

        // ---- local dist update + per-thread argmax (bit compare == float
        // compare for non-negative f32; strict > keeps lowest idx since idx
        // ascends within the thread -> matches jnp.argmax first-max) ----
        unsigned bdb = 0u, btl = 0u;
#pragma unroll
        for (int i = 0; i < PPT / 2; ++i) {
            u64 dx = addx2(x2[i], nsx);
            u64 dy = addx2(y2[i], nsy);
            u64 dz = addx2(z2[i], nsz);
            // unfused, left-to-right (dx*dx + dy*dy) + dz*dz == reference
            u64 s = addx2(addx2(mulx2(dx, dx), mulx2(dy, dy)), mulx2(dz, dz));
            float d0, d1; f2unpack(d0, d1, s);
            float nd0 = fminf(dist[2 * i], d0);
            float nd1 = fminf(dist[2 * i + 1], d1);
            dist[2 * i] = nd0; dist[2 * i + 1] = nd1;
            unsigned db0 = __float_as_uint(nd0);
            unsigned db1 = __float_as_uint(nd1);
            if (db0 > bdb) { bdb = db0; btl = tail[2 * i]; }
            if (db1 > bdb) { bdb = db1; btl = tail[2 * i + 1]; }
        }

        // ---- warp argmax: max dist-bits, tie -> max tail (= lowest idx) ----
        unsigned m  = __reduce_max_sync(0xFFFFFFFFu, bdb);
        unsigned mt = __reduce_max_sync(0xFFFFFFFFu, (bdb == m) ? btl : 0u);
        if (lane == 0) { s_db[wid] = m; s_tl[wid] = mt; }
        __syncthreads();

        if (wid == 0) {
            // ---- block argmax over NW warp winners ----
            unsigned db2 = (lane < NW) ? s_db[lane] : 0u;
            unsigned tl2 = (lane < NW) ? s_tl[lane] : 0u;
            unsigned m2  = __reduce_max_sync(0xFFFFFFFFu, db2);
            unsigned mt2 = __reduce_max_sync(0xFFFFFFFFu, (db2 == m2) ? tl2 : 0u);

            Line* L = &g_line[t & 1][b];
            if (lane == 0) {
                u64 key = ((u64)(unsigned)t << 49) | ((u64)m2 << 17) | (u64)mt2;
                red_max_u64(&L->key, key);      // batch argmax done by L2
                red_add_rel(&L->cnt, 1u);       // release: my max visible first
            }

            // ---- detect: poll ONLY the 4B counter (broadcast address);
            // >= is safe: this parity line passes 'target' only after every
            // CTA (incl. us) consumed round t (round t+2 publish requires
            // all CTAs through t+1, which requires all through t) ----
            const unsigned target = (unsigned)CPB * (unsigned)((t + 1) >> 1);
            while (ld_acq_u32(&L->cnt) < target) { }

            // ---- ordered AFTER the acquire: final key, tear-free 64b load.
            // All 64 maxes happened-before their release-adds; acquire on the
            // summed counter makes them all visible here. ----
            u64 key = ld_rlx_u64(&L->key);
            unsigned idx = 0x1FFFFu - (unsigned)(key & 0x1FFFFu);
            float4 w = pts[(size_t)b * NPB + idx];   // broadcast L2 hit
            if (lane == 0) {
                s_new[0] = w.y; s_new[1] = w.z; s_new[2] = w.w;
                if (c == 0)
                    ((float4*)out)[(size_t)b * MSAMP + t] = w;  // {b,x,y,z}
            }
        }
        __syncthreads();
        sx = s_new[0]; sy = s_new[1]; sz = s_new[2];
    }
}

extern "C" void kernel_launch(void* const* d_in, const int* in_sizes, int n_in,
                              void* d_out, int out_size) {
    (void)in_sizes; (void)n_in; (void)out_size;
    const float4* pts = (const float4*)d_in[0];
    reset_kernel<<<1, 32>>>();                    // clears lines each replay
    dim3 grid(CPB, NBATCH);
    fps_kernel<<<grid, TPB>>>(pts, (float*)d_out);
}